// round 8
// baseline (speedup 1.0000x reference)
#include <cuda_runtime.h>
#include <cuda_bf16.h>
#include <cstdint>

// Problem constants
#define B_      16
#define CIN     128
#define COUT    128
#define H_      128
#define W_      128
#define S_      512
#define EPS_    1e-8f

// Tiling: block computes 32 co x 16 h x 32 w; thread computes 8 co x 8 w
#define TCO 32
#define TH  16
#define TW  32
#define TCI 8
#define XROW 36   // 34 used cols (32 + 2 halo), padded to 36

// Scratch (tiny): modulation scales + demod coefs
__device__ float g_s[B_ * CIN];
__device__ float g_w2[COUT * CIN];
__device__ float g_decoef[B_ * COUT];

// ---- packed f32x2 helpers (sm_103a) --------------------------------------
__device__ __forceinline__ void ffma2(uint64_t& d, uint64_t a, uint64_t b) {
    asm("fma.rn.f32x2 %0, %1, %2, %0;" : "+l"(d) : "l"(a), "l"(b));
}
__device__ __forceinline__ uint64_t pack2(float lo, float hi) {
    uint64_t r;
    asm("mov.b64 %0, {%1, %2};" : "=l"(r) : "f"(lo), "f"(hi));
    return r;
}
__device__ __forceinline__ void unpack2(uint64_t v, float& lo, float& hi) {
    asm("mov.b64 {%0, %1}, %2;" : "=f"(lo), "=f"(hi) : "l"(v));
}

// ---------------------------------------------------------------------------
// Kernel 1: s[b][ci] = style[b] . mod_w[ci] + mod_b[ci]
__global__ void k_style(const float* __restrict__ style,
                        const float* __restrict__ mod_w,
                        const float* __restrict__ mod_b) {
    int b = blockIdx.x;
    int ci = threadIdx.x;
    const float* st = style + b * S_;
    const float* mw = mod_w + ci * S_;
    float acc = 0.f;
#pragma unroll 8
    for (int k = 0; k < S_; k++) acc = fmaf(st[k], mw[k], acc);
    g_s[b * CIN + ci] = acc + mod_b[ci];
}

// ---------------------------------------------------------------------------
// Kernel 2: W2[co][ci] = sum_k weight[co][ci][k]^2
__global__ void k_w2(const float* __restrict__ weight) {
    int i = blockIdx.x * blockDim.x + threadIdx.x;
    if (i >= COUT * CIN) return;
    const float* w = weight + i * 9;
    float acc = 0.f;
#pragma unroll
    for (int k = 0; k < 9; k++) acc = fmaf(w[k], w[k], acc);
    g_w2[i] = acc;
}

// ---------------------------------------------------------------------------
// Kernel 3: decoef[b][co] = rsqrt(sum_ci W2[co][ci]*s[b][ci]^2 + eps)
__global__ void k_decoef() {
    int i = blockIdx.x * blockDim.x + threadIdx.x;
    if (i >= B_ * COUT) return;
    int b = i / COUT;
    int co = i % COUT;
    const float* w2 = g_w2 + co * CIN;
    const float* sb = g_s + b * CIN;
    float acc = 0.f;
#pragma unroll 8
    for (int ci = 0; ci < CIN; ci++) {
        float sv = sb[ci];
        acc = fmaf(w2[ci], sv * sv, acc);
    }
    g_decoef[i] = rsqrtf(acc + EPS_);
}

// ---------------------------------------------------------------------------
// Main conv:
//   out[b,co,h,w] = decoef[b,co] * sum_{ci,kh,kw} (x*s)[b,ci,h+kh-1,w+kw-1] * weight[co,ci,kh,kw]
//
// grid: (W_/TW=4, H_/TH=8, B_*COUT/TCO=64), block: 256
// thread: tg=tid>>6 (co group of 8), lid=tid&63, th=lid>>2 (row 0..15),
//         tw=lid&3 (w octet). Thread computes co = tg*8+0..7, w = tw*8+0..7.
// x row per (ci,kh): 10 floats loaded as 2x LDS.128 + 1x LDS.64, reused
// across all kw and all 8 co -> LDS:FFMA2 = 27:96 per (ci,kh), FMA-bound.
// Bank check (x, quarter-warp of 8 lanes, LDS.128): bank = (th*36 + tw*8)%32
// = th*4 + tw*8; th 0..1, tw 0..3 -> spans {0,8,16,24,4,12,20,28}+0..3 = all
// 32 banks, conflict-free. Weight LDS.64 is warp-uniform -> broadcast.
__global__ void __launch_bounds__(256, 2)
k_conv(const float* __restrict__ x,
       const float* __restrict__ weight,
       float* __restrict__ out) {
    __shared__ __align__(16) float  xs[TCI][TH + 2][XROW];  // scaled input patch
    __shared__ __align__(8)  float2 ws[TCI][TCO][9];        // weights dup (w,w)

    const int b   = blockIdx.z >> 2;
    const int co0 = (blockIdx.z & 3) * TCO;
    const int h0  = blockIdx.y * TH;
    const int w0  = blockIdx.x * TW;

    const int tid = threadIdx.x;
    const int tg  = tid >> 6;            // 0..3
    const int lid = tid & 63;
    const int th  = lid >> 2;            // 0..15
    const int tw8 = (lid & 3) * 8;       // 0,8,16,24

    const float* sb = g_s + b * CIN;

    uint64_t acc[8][4];
#pragma unroll
    for (int r = 0; r < 8; r++)
#pragma unroll
        for (int j = 0; j < 4; j++) acc[r][j] = 0ull;

    for (int ci0 = 0; ci0 < CIN; ci0 += TCI) {
        // ---- load scaled input patch: TCI x 18 rows x 34 cols (pad to 36) ----
        for (int i = tid; i < TCI * 18 * XROW; i += 256) {
            int ci  = i / (18 * XROW);
            int rem = i - ci * (18 * XROW);
            int hh  = rem / XROW;
            int ww  = rem - hh * XROW;
            if (ww < TW + 2) {
                int gh = h0 + hh - 1;
                int gw = w0 + ww - 1;
                float v = 0.f;
                if (gh >= 0 && gh < H_ && gw >= 0 && gw < W_)
                    v = x[(((size_t)b * CIN + ci0 + ci) * H_ + gh) * W_ + gw] * sb[ci0 + ci];
                xs[ci][hh][ww] = v;
            }
        }
        // ---- load weights (32 co x 8 ci x 9), duplicated into (w,w) ----
        for (int i = tid; i < TCO * TCI * 9; i += 256) {
            int co  = i / (TCI * 9);
            int rem = i - co * (TCI * 9);
            int ci  = rem / 9;
            int k   = rem - ci * 9;
            float wv = weight[((size_t)(co0 + co) * CIN + ci0 + ci) * 9 + k];
            ws[ci][co][k] = make_float2(wv, wv);
        }
        __syncthreads();

        // ---- compute ----
#pragma unroll 1
        for (int ci = 0; ci < TCI; ci++) {
#pragma unroll
            for (int kh = 0; kh < 3; kh++) {
                const float* xr = &xs[ci][th + kh][tw8];
                float4 xa = *reinterpret_cast<const float4*>(xr);
                float4 xb = *reinterpret_cast<const float4*>(xr + 4);
                float2 xc = *reinterpret_cast<const float2*>(xr + 8);
                // even pairs (for kw=0 and kw=2)
                uint64_t P0 = pack2(xa.x, xa.y);
                uint64_t P1 = pack2(xa.z, xa.w);
                uint64_t P2 = pack2(xb.x, xb.y);
                uint64_t P3 = pack2(xb.z, xb.w);
                uint64_t P4 = pack2(xc.x, xc.y);
                // odd pairs (for kw=1)
                uint64_t Q0 = pack2(xa.y, xa.z);
                uint64_t Q1 = pack2(xa.w, xb.x);
                uint64_t Q2 = pack2(xb.y, xb.z);
                uint64_t Q3 = pack2(xb.w, xc.x);
#pragma unroll
                for (int r = 0; r < 8; r++) {
                    const uint64_t* wp =
                        reinterpret_cast<const uint64_t*>(&ws[ci][tg * 8 + r][kh * 3]);
                    uint64_t wv0 = wp[0];
                    uint64_t wv1 = wp[1];
                    uint64_t wv2 = wp[2];
                    ffma2(acc[r][0], P0, wv0);
                    ffma2(acc[r][1], P1, wv0);
                    ffma2(acc[r][2], P2, wv0);
                    ffma2(acc[r][3], P3, wv0);
                    ffma2(acc[r][0], Q0, wv1);
                    ffma2(acc[r][1], Q1, wv1);
                    ffma2(acc[r][2], Q2, wv1);
                    ffma2(acc[r][3], Q3, wv1);
                    ffma2(acc[r][0], P1, wv2);
                    ffma2(acc[r][1], P2, wv2);
                    ffma2(acc[r][2], P3, wv2);
                    ffma2(acc[r][3], P4, wv2);
                }
            }
        }
        __syncthreads();
    }

    // ---- epilogue: demodulate + vectorized store (2x STG.128 per co) ----
#pragma unroll
    for (int r = 0; r < 8; r++) {
        int co = co0 + tg * 8 + r;
        float d = g_decoef[b * COUT + co];
        size_t base = (((size_t)b * COUT + co) * H_ + (h0 + th)) * W_ + w0 + tw8;
        float o[8];
        unpack2(acc[r][0], o[0], o[1]);
        unpack2(acc[r][1], o[2], o[3]);
        unpack2(acc[r][2], o[4], o[5]);
        unpack2(acc[r][3], o[6], o[7]);
        float4 v0 = make_float4(o[0] * d, o[1] * d, o[2] * d, o[3] * d);
        float4 v1 = make_float4(o[4] * d, o[5] * d, o[6] * d, o[7] * d);
        *reinterpret_cast<float4*>(&out[base])     = v0;
        *reinterpret_cast<float4*>(&out[base + 4]) = v1;
    }
}

// ---------------------------------------------------------------------------
extern "C" void kernel_launch(void* const* d_in, const int* in_sizes, int n_in,
                              void* d_out, int out_size) {
    const float* x      = (const float*)d_in[0];  // [16,128,128,128]
    const float* style  = (const float*)d_in[1];  // [16,512]
    const float* weight = (const float*)d_in[2];  // [1,128,128,3,3]
    const float* mod_w  = (const float*)d_in[3];  // [128,512]
    const float* mod_b  = (const float*)d_in[4];  // [128]
    float* out = (float*)d_out;                   // [16,128,128,128]

    k_style<<<B_, CIN>>>(style, mod_w, mod_b);
    k_w2<<<(COUT * CIN + 255) / 256, 256>>>(weight);
    k_decoef<<<(B_ * COUT + 255) / 256, 256>>>();

    dim3 grid(W_ / TW, H_ / TH, B_ * (COUT / TCO));  // 4 x 8 x 64
    k_conv<<<grid, 256>>>(x, weight, out);
}

// round 11
// speedup vs baseline: 1.2016x; 1.2016x over previous
#include <cuda_runtime.h>
#include <cuda_bf16.h>
#include <cstdint>

// Problem constants
#define B_      16
#define CIN     128
#define COUT    128
#define H_      128
#define W_      128
#define S_      512
#define EPS_    1e-8f

// Tiling: block = 32 co x 8 h x 64 w; thread = 8 co x 8 w
#define TCO 32
#define TH  8
#define TW  64
#define TCI 8
#define XPAIRS 34   // 33 used float2 pairs (66 cols = 64 + 2 halo), +1 pad

// Scratch (tiny)
__device__ float g_s[B_ * CIN];
__device__ float g_w2[COUT * CIN];
__device__ float g_decoef[B_ * COUT];

// ---- packed f32x2 helpers (sm_103a) --------------------------------------
__device__ __forceinline__ void ffma2(uint64_t& d, uint64_t a, uint64_t b) {
    asm("fma.rn.f32x2 %0, %1, %2, %0;" : "+l"(d) : "l"(a), "l"(b));
}
// (a.hi, b.lo) -> packed pair; ptxas resolves most of this to register aliasing
__device__ __forceinline__ uint64_t opair(uint64_t a, uint64_t b) {
    uint64_t r;
    asm("{\n\t"
        ".reg .b32 al, ah, bl, bh;\n\t"
        "mov.b64 {al, ah}, %1;\n\t"
        "mov.b64 {bl, bh}, %2;\n\t"
        "mov.b64 %0, {ah, bl};\n\t"
        "}" : "=l"(r) : "l"(a), "l"(b));
    return r;
}
__device__ __forceinline__ void unpack2(uint64_t v, float& lo, float& hi) {
    asm("mov.b64 {%0, %1}, %2;" : "=f"(lo), "=f"(hi) : "l"(v));
}

// ---------------------------------------------------------------------------
__global__ void k_style(const float* __restrict__ style,
                        const float* __restrict__ mod_w,
                        const float* __restrict__ mod_b) {
    int b = blockIdx.x;
    int ci = threadIdx.x;
    const float* st = style + b * S_;
    const float* mw = mod_w + ci * S_;
    float acc = 0.f;
#pragma unroll 8
    for (int k = 0; k < S_; k++) acc = fmaf(st[k], mw[k], acc);
    g_s[b * CIN + ci] = acc + mod_b[ci];
}

__global__ void k_w2(const float* __restrict__ weight) {
    int i = blockIdx.x * blockDim.x + threadIdx.x;
    if (i >= COUT * CIN) return;
    const float* w = weight + i * 9;
    float acc = 0.f;
#pragma unroll
    for (int k = 0; k < 9; k++) acc = fmaf(w[k], w[k], acc);
    g_w2[i] = acc;
}

__global__ void k_decoef() {
    int i = blockIdx.x * blockDim.x + threadIdx.x;
    if (i >= B_ * COUT) return;
    int b = i / COUT;
    int co = i % COUT;
    const float* w2 = g_w2 + co * CIN;
    const float* sb = g_s + b * CIN;
    float acc = 0.f;
#pragma unroll 8
    for (int ci = 0; ci < CIN; ci++) {
        float sv = sb[ci];
        acc = fmaf(w2[ci], sv * sv, acc);
    }
    g_decoef[i] = rsqrtf(acc + EPS_);
}

// ---------------------------------------------------------------------------
// Main conv:
//   out[b,co,h,w] = decoef[b,co] * sum_{ci,kh,kw} (x*s)[b,ci,h+kh-1,w+kw-1] * W[co,ci,kh,kw]
//
// grid: (W_/TW=2, H_/TH=16, B_*(COUT/TCO)=64) = 2048 blocks, block 256
// thread: tg = tid>>6 (co octet), lid = tid&63, th = lid>>3 (0..7, h row),
//         tw = lid&7 (w octet: w = w0 + tw*8 + 0..7).
// x smem: scalar floats at [ci][row][col] (col s -> global w0+s-1), but read
// in the mainloop as float2 pairs P_k = (col 2k, col 2k+1) via LDS.64 — the
// thread's even pairs E_j = P[4*tw+j], j=0..4. Odd (kw=1) pairs spliced from
// adjacent E's with opair() (~1 mov each). Weights pre-duplicated (w,w) in
// smem -> warp-uniform LDS.64 broadcast, zero packing movs.
// Per (ci,kh) per warp: 96 FFMA2 (192 pipe-cyc) vs ~35 LDS + ~6 movs -> FMA-bound.
__global__ void __launch_bounds__(256, 2)
k_conv(const float* __restrict__ x,
       const float* __restrict__ weight,
       float* __restrict__ out) {
    __shared__ __align__(16) float2 xs[TCI][TH + 2][XPAIRS];   // scaled input
    __shared__ __align__(16) float2 ws[TCI][TCO][10];          // (w,w) dup, 9 used

    const int b   = blockIdx.z >> 2;
    const int co0 = (blockIdx.z & 3) * TCO;
    const int h0  = blockIdx.y * TH;
    const int w0  = blockIdx.x * TW;

    const int tid = threadIdx.x;
    const int tg  = tid >> 6;          // 0..3
    const int lid = tid & 63;
    const int th  = lid >> 3;          // 0..7
    const int tw  = lid & 7;           // 0..7

    const float* sb = g_s + b * CIN;

    uint64_t acc[8][4];
#pragma unroll
    for (int r = 0; r < 8; r++)
#pragma unroll
        for (int j = 0; j < 4; j++) acc[r][j] = 0ull;

    for (int ci0 = 0; ci0 < CIN; ci0 += TCI) {
        // ---- build scaled input patch: TCI x 10 rows x 66 cols (scalar STS) ----
        float* xsf = reinterpret_cast<float*>(xs);
        for (int i = tid; i < TCI * 10 * 66; i += 256) {
            int ci  = i / 660;
            int rem = i - ci * 660;
            int row = rem / 66;
            int col = rem - row * 66;
            int gh = h0 + row - 1;
            int gw = w0 + col - 1;
            float v = 0.f;
            if (gh >= 0 && gh < H_ && gw >= 0 && gw < W_)
                v = x[(((size_t)b * CIN + ci0 + ci) * H_ + gh) * W_ + gw] * sb[ci0 + ci];
            xsf[(ci * 10 + row) * (2 * XPAIRS) + col] = v;
        }
        // ---- weights (32 co x 8 ci x 9), duplicated (w,w) ----
        for (int i = tid; i < TCO * TCI * 9; i += 256) {
            int co  = i / (TCI * 9);
            int rem = i - co * (TCI * 9);
            int ci  = rem / 9;
            int k   = rem - ci * 9;
            float wv = weight[((size_t)(co0 + co) * CIN + ci0 + ci) * 9 + k];
            ws[ci][co][k] = make_float2(wv, wv);
        }
        __syncthreads();

        // ---- compute ----
#pragma unroll 1
        for (int ci = 0; ci < TCI; ci++) {
#pragma unroll
            for (int kh = 0; kh < 3; kh++) {
                const uint64_t* xp =
                    reinterpret_cast<const uint64_t*>(&xs[ci][th + kh][0]) + 4 * tw;
                uint64_t E0 = xp[0];
                uint64_t E1 = xp[1];
                uint64_t E2 = xp[2];
                uint64_t E3 = xp[3];
                uint64_t E4 = xp[4];
                uint64_t O0 = opair(E0, E1);
                uint64_t O1 = opair(E1, E2);
                uint64_t O2 = opair(E2, E3);
                uint64_t O3 = opair(E3, E4);
#pragma unroll
                for (int r = 0; r < 8; r++) {
                    const uint64_t* wp =
                        reinterpret_cast<const uint64_t*>(&ws[ci][tg * 8 + r][kh * 3]);
                    uint64_t W0 = wp[0];
                    uint64_t W1 = wp[1];
                    uint64_t W2 = wp[2];
                    ffma2(acc[r][0], E0, W0);
                    ffma2(acc[r][1], E1, W0);
                    ffma2(acc[r][2], E2, W0);
                    ffma2(acc[r][3], E3, W0);
                    ffma2(acc[r][0], O0, W1);
                    ffma2(acc[r][1], O1, W1);
                    ffma2(acc[r][2], O2, W1);
                    ffma2(acc[r][3], O3, W1);
                    ffma2(acc[r][0], E1, W2);
                    ffma2(acc[r][1], E2, W2);
                    ffma2(acc[r][2], E3, W2);
                    ffma2(acc[r][3], E4, W2);
                }
            }
        }
        __syncthreads();
    }

    // ---- epilogue: demodulate + 2x STG.128 per co ----
#pragma unroll
    for (int r = 0; r < 8; r++) {
        int co = co0 + tg * 8 + r;
        float d = g_decoef[b * COUT + co];
        size_t base = (((size_t)b * COUT + co) * H_ + (h0 + th)) * W_ + w0 + tw * 8;
        float o[8];
        unpack2(acc[r][0], o[0], o[1]);
        unpack2(acc[r][1], o[2], o[3]);
        unpack2(acc[r][2], o[4], o[5]);
        unpack2(acc[r][3], o[6], o[7]);
        float4 v0 = make_float4(o[0] * d, o[1] * d, o[2] * d, o[3] * d);
        float4 v1 = make_float4(o[4] * d, o[5] * d, o[6] * d, o[7] * d);
        *reinterpret_cast<float4*>(&out[base])     = v0;
        *reinterpret_cast<float4*>(&out[base + 4]) = v1;
    }
}

// ---------------------------------------------------------------------------
extern "C" void kernel_launch(void* const* d_in, const int* in_sizes, int n_in,
                              void* d_out, int out_size) {
    const float* x      = (const float*)d_in[0];  // [16,128,128,128]
    const float* style  = (const float*)d_in[1];  // [16,512]
    const float* weight = (const float*)d_in[2];  // [1,128,128,3,3]
    const float* mod_w  = (const float*)d_in[3];  // [128,512]
    const float* mod_b  = (const float*)d_in[4];  // [128]
    float* out = (float*)d_out;                   // [16,128,128,128]

    k_style<<<B_, CIN>>>(style, mod_w, mod_b);
    k_w2<<<(COUT * CIN + 255) / 256, 256>>>(weight);
    k_decoef<<<(B_ * COUT + 255) / 256, 256>>>();

    dim3 grid(W_ / TW, H_ / TH, B_ * (COUT / TCO));  // 2 x 16 x 64
    k_conv<<<grid, 256>>>(x, weight, out);
}